// round 9
// baseline (speedup 1.0000x reference)
#include <cuda_runtime.h>
#include <cuda_bf16.h>
#include <cstdint>

#define H    128
#define HH   64
#define NMAX 100000
#define EMAX 800000
#define TM   128

// ---------------------------------------------------------------------------
__device__ float g_invfeat[(size_t)NMAX * H];
__device__ float g_nsum[(size_t)NMAX * H];
__device__ float g_res[(size_t)NMAX * H];
__device__ int   g_deg[NMAX];
__device__ int   g_off[NMAX + 1];
__device__ int   g_cur[NMAX];
__device__ unsigned int g_perm[EMAX];
__device__ int   g_idx[NMAX];
__device__ int   g_cnt;

__device__ __forceinline__ float lrelu(float x) { return x >= 0.f ? x : 0.01f * x; }

// ---------------------------------------------------------------------------
// smem layout: weights hi/lo planes + biases only (~91KB)
#define XSB 272      // w1 row stride: (128+8) bf16
#define HSB 144      // w2/w3 row stride: (64+8) bf16
#define OW1H 0
#define OW1L 17408
#define OW2H 34816
#define OW2L 44032
#define OW3H 53248
#define OW3L 71680
#define OB1  90112
#define OB2  90368
#define OB3  90624
#define SMEM_BYTES 91648

__device__ __forceinline__ uint32_t smem_u32(const void* p) {
    uint32_t a;
    asm("{ .reg .u64 t; cvta.to.shared.u64 t, %1; cvt.u32.u64 %0, t; }" : "=r"(a) : "l"(p));
    return a;
}

__device__ __forceinline__ void ldm_x4(uint32_t addr, uint32_t r[4]) {
    asm volatile("ldmatrix.sync.aligned.m8n8.x4.shared.b16 {%0,%1,%2,%3}, [%4];"
                 : "=r"(r[0]), "=r"(r[1]), "=r"(r[2]), "=r"(r[3]) : "r"(addr));
}

__device__ __forceinline__ void mma_bf16(float c[4], const uint32_t a[4],
                                         uint32_t b0, uint32_t b1) {
    asm volatile("mma.sync.aligned.m16n8k16.row.col.f32.bf16.bf16.f32 "
                 "{%0,%1,%2,%3}, {%4,%5,%6,%7}, {%8,%9}, {%0,%1,%2,%3};"
                 : "+f"(c[0]), "+f"(c[1]), "+f"(c[2]), "+f"(c[3])
                 : "r"(a[0]), "r"(a[1]), "r"(a[2]), "r"(a[3]), "r"(b0), "r"(b1));
}

// split pair (x=even col, y=odd col) into bf16x2 hi and lo words
__device__ __forceinline__ void split2(float x, float y, uint32_t& hi, uint32_t& lo) {
    __nv_bfloat162 h = __floats2bfloat162_rn(x, y);
    float rx = x - __bfloat162float(h.x);
    float ry = y - __bfloat162float(h.y);
    __nv_bfloat162 l = __floats2bfloat162_rn(rx, ry);
    hi = *reinterpret_cast<uint32_t*>(&h);
    lo = *reinterpret_cast<uint32_t*>(&l);
}

// term sweep: 8 distinct accumulators between same-acc reuse
__device__ __forceinline__ void sweep(float acc[8][4], const uint32_t a[4],
                                      const uint32_t b[4][4]) {
    #pragma unroll
    for (int np = 0; np < 4; np++) {
        mma_bf16(acc[2*np],   a, b[np][0], b[np][1]);
        mma_bf16(acc[2*np+1], a, b[np][2], b[np][3]);
    }
}

// C-frag (8 n-tiles) -> next layer A-frags (4 k-chunks), bias+lrelu+split in regs
__device__ __forceinline__ void epi_frag(const float a[8][4], const float* bs, int t,
                                         uint32_t fh[4][4], uint32_t fl[4][4]) {
    #pragma unroll
    for (int k = 0; k < 4; k++) {
        int ce = 16 * k + 2 * t, co = ce + 8;
        float be0 = bs[ce], be1 = bs[ce + 1], bo0 = bs[co], bo1 = bs[co + 1];
        split2(lrelu(a[2*k][0] + be0),   lrelu(a[2*k][1] + be1),   fh[k][0], fl[k][0]);
        split2(lrelu(a[2*k][2] + be0),   lrelu(a[2*k][3] + be1),   fh[k][1], fl[k][1]);
        split2(lrelu(a[2*k+1][0] + bo0), lrelu(a[2*k+1][1] + bo1), fh[k][2], fl[k][2]);
        split2(lrelu(a[2*k+1][2] + bo0), lrelu(a[2*k+1][3] + bo1), fh[k][3], fl[k][3]);
    }
}

// ---------------------------------------------------------------------------
__global__ void zero_kernel(int n) {
    int i = blockIdx.x * blockDim.x + threadIdx.x;
    if (i < n) g_deg[i] = 0;
    if (i == 0) g_cnt = 0;
}

__global__ void hist_kernel(const int* __restrict__ dst, int nedges) {
    int e = blockIdx.x * blockDim.x + threadIdx.x;
    if (e < nedges) atomicAdd(&g_deg[dst[e]], 1);
}

// single-block exclusive scan of g_deg -> g_off / g_cur (1024 thr, 8 elems/thr)
__global__ __launch_bounds__(1024) void scan_kernel(int n) {
    __shared__ int ssum[1024];
    __shared__ int scarry;
    const int tid = threadIdx.x;
    if (tid == 0) scarry = 0;
    __syncthreads();

    for (int base = 0; base < n; base += 8192) {
        int i0 = base + tid * 8;
        int v[8], lsum = 0;
        #pragma unroll
        for (int j = 0; j < 8; j++) {
            v[j] = (i0 + j < n) ? g_deg[i0 + j] : 0;
            lsum += v[j];
        }
        ssum[tid] = lsum;
        __syncthreads();
        // Hillis-Steele inclusive scan over 1024 thread sums
        for (int d = 1; d < 1024; d <<= 1) {
            int tval = (tid >= d) ? ssum[tid - d] : 0;
            __syncthreads();
            ssum[tid] += tval;
            __syncthreads();
        }
        int excl = scarry + ssum[tid] - lsum;
        #pragma unroll
        for (int j = 0; j < 8; j++) {
            if (i0 + j < n) { g_off[i0 + j] = excl; g_cur[i0 + j] = excl; }
            excl += v[j];
        }
        int tot = ssum[1023];
        __syncthreads();
        if (tid == 0) scarry += tot;
        __syncthreads();
    }
    if (tid == 0) g_off[n] = scarry;
}

__global__ void fill_kernel(const int* __restrict__ src, const int* __restrict__ dst,
                            const int* __restrict__ r, int nedges) {
    int e = blockIdx.x * blockDim.x + threadIdx.x;
    if (e >= nedges) return;
    int pos = atomicAdd(&g_cur[dst[e]], 1);
    g_perm[pos] = (unsigned int)src[e] | (r[e] ? 0x80000000u : 0u);
}

// warp per dst node: sum messages, write MEAN (no atomics, no pre-zero)
__global__ __launch_bounds__(256) void aggregate_kernel(
    const float* __restrict__ feat, int n) {
    int w    = (blockIdx.x * blockDim.x + threadIdx.x) >> 5;
    int lane = threadIdx.x & 31;
    if (w >= n) return;
    int beg = g_off[w], end = g_off[w + 1];
    float4 s = make_float4(0.f, 0.f, 0.f, 0.f);
    for (int i = beg; i < end; i++) {
        unsigned int p = g_perm[i];
        const float* tab = (p & 0x80000000u) ? g_invfeat : feat;
        int sidx = (int)(p & 0x7FFFFFFFu);
        float4 v = *reinterpret_cast<const float4*>(tab + (size_t)sidx * H + lane * 4);
        s.x += v.x; s.y += v.y; s.z += v.z; s.w += v.w;
    }
    int deg = end - beg;
    float sc = 1.f / (float)max(deg, 1);
    s.x *= sc; s.y *= sc; s.z *= sc; s.w *= sc;
    *reinterpret_cast<float4*>(g_nsum + (size_t)w * H + lane * 4) = s;
}

// ---------------------------------------------------------------------------
// warp per row: inv==1 rows -> append to index list; inv==0 rows -> copy res->out
__global__ __launch_bounds__(256) void compact_kernel(
    const int* __restrict__ inv, const float* __restrict__ res,
    float* __restrict__ out, int n) {
    int w    = (blockIdx.x * blockDim.x + threadIdx.x) >> 5;
    int lane = threadIdx.x & 31;
    int nw   = (gridDim.x * blockDim.x) >> 5;
    for (int row = w; row < n; row += nw) {
        if (inv[row] == 1) {
            if (lane == 0) {
                int p = atomicAdd(&g_cnt, 1);
                g_idx[p] = row;
            }
        } else {
            float4 v = reinterpret_cast<const float4*>(res + (size_t)row * H)[lane];
            reinterpret_cast<float4*>(out + (size_t)row * H)[lane] = v;
        }
    }
}

// ---------------------------------------------------------------------------
// Fused 3-layer MLP: bf16 split mma.sync, activations register-resident.
__global__ __launch_bounds__(256, 2) void mlp3_mma(
    const float* __restrict__ in, float* __restrict__ out,
    const float* __restrict__ w1, const float* __restrict__ b1,
    const float* __restrict__ w2, const float* __restrict__ b2,
    const float* __restrict__ w3, const float* __restrict__ b3,
    const int* __restrict__ rowidx, const int* __restrict__ cnt_dev,
    int nrows) {
    extern __shared__ char wp[];
    const uint32_t sb = smem_u32(wp);

    const int tid  = threadIdx.x;
    const int wid  = tid >> 5;
    const int lane = tid & 31;

    // ---- stage weights bf16 hi/lo, [n][k] row-major padded ----
    for (int idx = tid; idx < HH * H; idx += 256) {      // w1 [64][128]
        int n = idx >> 7, k = idx & 127;
        float v = w1[idx];
        __nv_bfloat16 h = __float2bfloat16_rn(v);
        __nv_bfloat16 l = __float2bfloat16_rn(v - __bfloat162float(h));
        *(__nv_bfloat16*)(wp + OW1H + n * XSB + k * 2) = h;
        *(__nv_bfloat16*)(wp + OW1L + n * XSB + k * 2) = l;
    }
    for (int idx = tid; idx < HH * HH; idx += 256) {     // w2 [64][64]
        int n = idx >> 6, k = idx & 63;
        float v = w2[idx];
        __nv_bfloat16 h = __float2bfloat16_rn(v);
        __nv_bfloat16 l = __float2bfloat16_rn(v - __bfloat162float(h));
        *(__nv_bfloat16*)(wp + OW2H + n * HSB + k * 2) = h;
        *(__nv_bfloat16*)(wp + OW2L + n * HSB + k * 2) = l;
    }
    for (int idx = tid; idx < H * HH; idx += 256) {      // w3 [128][64]
        int n = idx >> 6, k = idx & 63;
        float v = w3[idx];
        __nv_bfloat16 h = __float2bfloat16_rn(v);
        __nv_bfloat16 l = __float2bfloat16_rn(v - __bfloat162float(h));
        *(__nv_bfloat16*)(wp + OW3H + n * HSB + k * 2) = h;
        *(__nv_bfloat16*)(wp + OW3L + n * HSB + k * 2) = l;
    }
    if (tid < HH) {
        ((float*)(wp + OB1))[tid] = b1[tid];
        ((float*)(wp + OB2))[tid] = b2[tid];
    }
    if (tid < H) ((float*)(wp + OB3))[tid] = b3[tid];
    __syncthreads();

    const float* b1s = (const float*)(wp + OB1);
    const float* b2s = (const float*)(wp + OB2);
    const float* b3s = (const float*)(wp + OB3);

    const int m0 = wid * 16;
    const int g  = lane >> 2;        // 0..7
    const int t  = lane & 3;         // 0..3

    // B-frag ldmatrix lane addressing
    const int b_row = (lane & 7) + ((lane >> 4) << 3);
    const int b_kof = ((lane >> 3) & 1) * 16;
    const uint32_t bw1h = sb + OW1H + b_row * XSB + b_kof;
    const uint32_t bw1l = sb + OW1L + b_row * XSB + b_kof;
    const uint32_t bw2h = sb + OW2H + b_row * HSB + b_kof;
    const uint32_t bw2l = sb + OW2L + b_row * HSB + b_kof;
    const uint32_t bw3h = sb + OW3H + b_row * HSB + b_kof;
    const uint32_t bw3l = sb + OW3L + b_row * HSB + b_kof;

    const int nr = (cnt_dev != nullptr) ? *cnt_dev : nrows;
    const int ntiles = (nr + TM - 1) / TM;

    for (int tile = blockIdx.x; tile < ntiles; tile += gridDim.x) {
        const int row0  = tile * TM;
        const int rowg_l  = row0 + m0 + g;
        const int rowg8_l = rowg_l + 8;
        const bool okg  = rowg_l  < nr;
        const bool okg8 = rowg8_l < nr;
        const int rowg  = (rowidx != nullptr) ? (okg  ? rowidx[rowg_l]  : 0) : rowg_l;
        const int rowg8 = (rowidx != nullptr) ? (okg8 ? rowidx[rowg8_l] : 0) : rowg8_l;

        const float* rp  = in + (size_t)rowg  * H + 2 * t;
        const float* rp8 = in + (size_t)rowg8 * H + 2 * t;

        // ================= layer 1: K=128, N=64 =================
        float acc[8][4] = {};
        #pragma unroll
        for (int kt = 0; kt < 8; kt++) {
            float2 p0 = okg  ? *(const float2*)(rp  + kt * 16)     : make_float2(0.f, 0.f);
            float2 p1 = okg8 ? *(const float2*)(rp8 + kt * 16)     : make_float2(0.f, 0.f);
            float2 p2 = okg  ? *(const float2*)(rp  + kt * 16 + 8) : make_float2(0.f, 0.f);
            float2 p3 = okg8 ? *(const float2*)(rp8 + kt * 16 + 8) : make_float2(0.f, 0.f);
            uint32_t ah[4], al[4];
            split2(p0.x, p0.y, ah[0], al[0]);
            split2(p1.x, p1.y, ah[1], al[1]);
            split2(p2.x, p2.y, ah[2], al[2]);
            split2(p3.x, p3.y, ah[3], al[3]);

            uint32_t bh[4][4], bl[4][4];
            #pragma unroll
            for (int np = 0; np < 4; np++) {
                ldm_x4(bw1h + np * 16 * XSB + kt * 32, bh[np]);
                ldm_x4(bw1l + np * 16 * XSB + kt * 32, bl[np]);
            }
            sweep(acc, ah, bh);
            sweep(acc, al, bh);
            sweep(acc, ah, bl);
        }

        // epi 1 -> layer-2 A frags (registers)
        uint32_t a2h[4][4], a2l[4][4];
        epi_frag(acc, b1s, t, a2h, a2l);

        // ================= layer 2: K=64, N=64 =================
        float acc2[8][4] = {};
        #pragma unroll
        for (int kt = 0; kt < 4; kt++) {
            uint32_t bh[4][4], bl[4][4];
            #pragma unroll
            for (int np = 0; np < 4; np++) {
                ldm_x4(bw2h + np * 16 * HSB + kt * 32, bh[np]);
                ldm_x4(bw2l + np * 16 * HSB + kt * 32, bl[np]);
            }
            sweep(acc2, a2h[kt], bh);
            sweep(acc2, a2l[kt], bh);
            sweep(acc2, a2h[kt], bl);
        }

        // epi 2 -> layer-3 A frags
        uint32_t a3h[4][4], a3l[4][4];
        epi_frag(acc2, b2s, t, a3h, a3l);

        // ================= layer 3: K=64, N=128 (two halves) =================
        #pragma unroll
        for (int nh = 0; nh < 2; nh++) {
            float acc3[8][4] = {};
            #pragma unroll
            for (int kt = 0; kt < 4; kt++) {
                uint32_t bh[4][4], bl[4][4];
                #pragma unroll
                for (int np = 0; np < 4; np++) {
                    uint32_t boff = (nh * 64 + np * 16) * HSB + kt * 32;
                    ldm_x4(bw3h + boff, bh[np]);
                    ldm_x4(bw3l + boff, bl[np]);
                }
                sweep(acc3, a3h[kt], bh);
                sweep(acc3, a3l[kt], bh);
                sweep(acc3, a3h[kt], bl);
            }
            #pragma unroll
            for (int nt = 0; nt < 8; nt++) {
                int col = nh * 64 + nt * 8 + 2 * t;
                float bx = b3s[col], by = b3s[col + 1];
                if (okg) {
                    float2 v = make_float2(acc3[nt][0] + bx, acc3[nt][1] + by);
                    *reinterpret_cast<float2*>(out + (size_t)rowg * H + col) = v;
                }
                if (okg8) {
                    float2 v = make_float2(acc3[nt][2] + bx, acc3[nt][3] + by);
                    *reinterpret_cast<float2*>(out + (size_t)rowg8 * H + col) = v;
                }
            }
        }
    }
}

// ---------------------------------------------------------------------------
extern "C" void kernel_launch(void* const* d_in, const int* in_sizes, int n_in,
                              void* d_out, int out_size) {
    const float* feat   = (const float*)d_in[0];
    const int*   src    = (const int*)d_in[1];
    const int*   dst    = (const int*)d_in[2];
    const int*   r      = (const int*)d_in[3];
    const int*   inv    = (const int*)d_in[4];
    const float* inv_w1 = (const float*)d_in[5];
    const float* inv_b1 = (const float*)d_in[6];
    const float* inv_w2 = (const float*)d_in[7];
    const float* inv_b2 = (const float*)d_in[8];
    const float* inv_w3 = (const float*)d_in[9];
    const float* inv_b3 = (const float*)d_in[10];
    const float* and_w1 = (const float*)d_in[11];
    const float* and_b1 = (const float*)d_in[12];
    const float* and_w2 = (const float*)d_in[13];
    const float* and_b2 = (const float*)d_in[14];
    const float* and_w3 = (const float*)d_in[15];
    const float* and_b3 = (const float*)d_in[16];

    const int n = in_sizes[0] / H;
    const int e = in_sizes[1];

    float *invfeat, *nsum, *res;
    int *idxl, *cnt;
    cudaGetSymbolAddress((void**)&invfeat, g_invfeat);
    cudaGetSymbolAddress((void**)&nsum,    g_nsum);
    cudaGetSymbolAddress((void**)&res,     g_res);
    cudaGetSymbolAddress((void**)&idxl,    g_idx);
    cudaGetSymbolAddress((void**)&cnt,     g_cnt);

    cudaFuncSetAttribute(mlp3_mma, cudaFuncAttributeMaxDynamicSharedMemorySize, SMEM_BYTES);

    const int egrid = (e + 255) / 256;
    const int ngrid = (n + 255) / 256;

    // 1. CSR build: zero counters -> histogram -> scan -> fill
    zero_kernel<<<ngrid, 256>>>(n);
    hist_kernel<<<egrid, 256>>>(dst, e);
    scan_kernel<<<1, 1024>>>(n);
    fill_kernel<<<egrid, 256>>>(src, dst, r, e);

    const int ntiles = (n + TM - 1) / TM;
    const int mgrid  = ntiles < 296 ? ntiles : 296;   // 2 CTAs/SM

    // 2. inv_feat = mlp3_inv(feat)   (overlaps nothing; ordered stream)
    mlp3_mma<<<mgrid, 256, SMEM_BYTES>>>(
        feat, invfeat, inv_w1, inv_b1, inv_w2, inv_b2, inv_w3, inv_b3,
        nullptr, nullptr, n);

    // 3. CSR aggregation: nsum = mean of messages per dst (no atomics)
    aggregate_kernel<<<(n * 32 + 255) / 256, 256>>>(feat, n);

    // 4. res = mlp3_and(nsum)
    mlp3_mma<<<mgrid, 256, SMEM_BYTES>>>(
        nsum, res, and_w1, and_b1, and_w2, and_b2, and_w3, and_b3,
        nullptr, nullptr, n);

    // 5a. compact inv==1 rows; copy inv==0 rows res->out
    compact_kernel<<<1024, 256>>>(inv, res, (float*)d_out, n);

    // 5b. out[idx] = mlp3_inv(res[idx]) for compacted rows
    mlp3_mma<<<296, 256, SMEM_BYTES>>>(
        res, (float*)d_out, inv_w1, inv_b1, inv_w2, inv_b2, inv_w3, inv_b3,
        idxl, cnt, n);
}

// round 10
// speedup vs baseline: 1.4328x; 1.4328x over previous
#include <cuda_runtime.h>
#include <cuda_bf16.h>
#include <cstdint>

#define H    128
#define HH   64
#define NMAX 100000
#define EMAX 800000
#define TM   128
#define SCB  8192          // scan elems per block
#define NSCB ((NMAX + SCB - 1) / SCB)

// ---------------------------------------------------------------------------
__device__ float g_invfeat[(size_t)NMAX * H];
__device__ float g_nsum[(size_t)NMAX * H];
__device__ float g_res[(size_t)NMAX * H];
__device__ int   g_deg[NMAX];
__device__ int   g_off[NMAX + 1];
__device__ int   g_cur[NMAX];
__device__ int   g_bsum[NSCB];
__device__ int   g_bbase[NSCB];
__device__ unsigned int g_perm[EMAX];
__device__ int   g_idx[NMAX];
__device__ int   g_cnt;

__device__ __forceinline__ float lrelu(float x) { return x >= 0.f ? x : 0.01f * x; }

// ---------------------------------------------------------------------------
// smem layout: weights hi/lo planes + biases only (~91KB)
#define XSB 272      // w1 row stride: (128+8) bf16
#define HSB 144      // w2/w3 row stride: (64+8) bf16
#define OW1H 0
#define OW1L 17408
#define OW2H 34816
#define OW2L 44032
#define OW3H 53248
#define OW3L 71680
#define OB1  90112
#define OB2  90368
#define OB3  90624
#define SMEM_BYTES 91648

__device__ __forceinline__ uint32_t smem_u32(const void* p) {
    uint32_t a;
    asm("{ .reg .u64 t; cvta.to.shared.u64 t, %1; cvt.u32.u64 %0, t; }" : "=r"(a) : "l"(p));
    return a;
}

__device__ __forceinline__ void ldm_x4(uint32_t addr, uint32_t r[4]) {
    asm volatile("ldmatrix.sync.aligned.m8n8.x4.shared.b16 {%0,%1,%2,%3}, [%4];"
                 : "=r"(r[0]), "=r"(r[1]), "=r"(r[2]), "=r"(r[3]) : "r"(addr));
}

__device__ __forceinline__ void mma_bf16(float c[4], const uint32_t a[4],
                                         uint32_t b0, uint32_t b1) {
    asm volatile("mma.sync.aligned.m16n8k16.row.col.f32.bf16.bf16.f32 "
                 "{%0,%1,%2,%3}, {%4,%5,%6,%7}, {%8,%9}, {%0,%1,%2,%3};"
                 : "+f"(c[0]), "+f"(c[1]), "+f"(c[2]), "+f"(c[3])
                 : "r"(a[0]), "r"(a[1]), "r"(a[2]), "r"(a[3]), "r"(b0), "r"(b1));
}

// split pair (x=even col, y=odd col) into bf16x2 hi and lo words
__device__ __forceinline__ void split2(float x, float y, uint32_t& hi, uint32_t& lo) {
    __nv_bfloat162 h = __floats2bfloat162_rn(x, y);
    float rx = x - __bfloat162float(h.x);
    float ry = y - __bfloat162float(h.y);
    __nv_bfloat162 l = __floats2bfloat162_rn(rx, ry);
    hi = *reinterpret_cast<uint32_t*>(&h);
    lo = *reinterpret_cast<uint32_t*>(&l);
}

// term sweep: 8 distinct accumulators between same-acc reuse
__device__ __forceinline__ void sweep(float acc[8][4], const uint32_t a[4],
                                      const uint32_t b[4][4]) {
    #pragma unroll
    for (int np = 0; np < 4; np++) {
        mma_bf16(acc[2*np],   a, b[np][0], b[np][1]);
        mma_bf16(acc[2*np+1], a, b[np][2], b[np][3]);
    }
}

// C-frag (8 n-tiles) -> next layer A-frags (4 k-chunks), bias+lrelu+split in regs
__device__ __forceinline__ void epi_frag(const float a[8][4], const float* bs, int t,
                                         uint32_t fh[4][4], uint32_t fl[4][4]) {
    #pragma unroll
    for (int k = 0; k < 4; k++) {
        int ce = 16 * k + 2 * t, co = ce + 8;
        float be0 = bs[ce], be1 = bs[ce + 1], bo0 = bs[co], bo1 = bs[co + 1];
        split2(lrelu(a[2*k][0] + be0),   lrelu(a[2*k][1] + be1),   fh[k][0], fl[k][0]);
        split2(lrelu(a[2*k][2] + be0),   lrelu(a[2*k][3] + be1),   fh[k][1], fl[k][1]);
        split2(lrelu(a[2*k+1][0] + bo0), lrelu(a[2*k+1][1] + bo1), fh[k][2], fl[k][2]);
        split2(lrelu(a[2*k+1][2] + bo0), lrelu(a[2*k+1][3] + bo1), fh[k][3], fl[k][3]);
    }
}

// ---------------------------------------------------------------------------
__global__ void zero_kernel(int n) {
    int i = blockIdx.x * blockDim.x + threadIdx.x;
    if (i < n) g_deg[i] = 0;
    if (i == 0) g_cnt = 0;
}

__global__ void hist_kernel(const int* __restrict__ dst, int nedges) {
    int e = blockIdx.x * blockDim.x + threadIdx.x;
    if (e < nedges) atomicAdd(&g_deg[dst[e]], 1);
}

// pass A: per-block sum of an 8192-elem chunk of g_deg
__global__ __launch_bounds__(1024) void scan_reduce_kernel(int n) {
    __shared__ int swarp[32];
    const int b = blockIdx.x, tid = threadIdx.x;
    int i0 = b * SCB + tid * 8;
    int lsum = 0;
    #pragma unroll
    for (int j = 0; j < 8; j++)
        lsum += (i0 + j < n) ? g_deg[i0 + j] : 0;
    // warp reduce
    for (int d = 16; d > 0; d >>= 1)
        lsum += __shfl_down_sync(0xFFFFFFFF, lsum, d);
    if ((tid & 31) == 0) swarp[tid >> 5] = lsum;
    __syncthreads();
    if (tid < 32) {
        int v = swarp[tid];
        for (int d = 16; d > 0; d >>= 1)
            v += __shfl_down_sync(0xFFFFFFFF, v, d);
        if (tid == 0) g_bsum[b] = v;
    }
}

// pass B: exclusive scan of the NSCB block sums (trivial)
__global__ void scan_base_kernel() {
    if (threadIdx.x == 0) {
        int acc = 0;
        for (int b = 0; b < NSCB; b++) { g_bbase[b] = acc; acc += g_bsum[b]; }
    }
}

// pass C: per-block local exclusive scan + base -> g_off / g_cur
__global__ __launch_bounds__(1024) void scan_write_kernel(int n) {
    __shared__ int ssum[1024];
    const int b = blockIdx.x, tid = threadIdx.x;
    int i0 = b * SCB + tid * 8;
    int v[8], lsum = 0;
    #pragma unroll
    for (int j = 0; j < 8; j++) {
        v[j] = (i0 + j < n) ? g_deg[i0 + j] : 0;
        lsum += v[j];
    }
    ssum[tid] = lsum;
    __syncthreads();
    for (int d = 1; d < 1024; d <<= 1) {
        int tval = (tid >= d) ? ssum[tid - d] : 0;
        __syncthreads();
        ssum[tid] += tval;
        __syncthreads();
    }
    int excl = g_bbase[b] + ssum[tid] - lsum;
    #pragma unroll
    for (int j = 0; j < 8; j++) {
        if (i0 + j < n) { g_off[i0 + j] = excl; g_cur[i0 + j] = excl; }
        excl += v[j];
    }
    if (b == gridDim.x - 1 && tid == 1023) g_off[n] = g_bbase[b] + ssum[1023];
}

__global__ void fill_kernel(const int* __restrict__ src, const int* __restrict__ dst,
                            const int* __restrict__ r, int nedges) {
    int e = blockIdx.x * blockDim.x + threadIdx.x;
    if (e >= nedges) return;
    int pos = atomicAdd(&g_cur[dst[e]], 1);
    g_perm[pos] = (unsigned int)src[e] | (r[e] ? 0x80000000u : 0u);
}

// warp per dst node, 4 gathers in flight: sum messages, write MEAN
__global__ __launch_bounds__(256) void aggregate_kernel(
    const float* __restrict__ feat, int n) {
    int w    = (blockIdx.x * blockDim.x + threadIdx.x) >> 5;
    int lane = threadIdx.x & 31;
    if (w >= n) return;
    int beg = g_off[w], end = g_off[w + 1];
    float4 s = make_float4(0.f, 0.f, 0.f, 0.f);
    int i = beg;
    for (; i + 4 <= end; i += 4) {
        unsigned int p0 = g_perm[i],     p1 = g_perm[i + 1];
        unsigned int p2 = g_perm[i + 2], p3 = g_perm[i + 3];
        const float* t0 = (p0 & 0x80000000u) ? g_invfeat : feat;
        const float* t1 = (p1 & 0x80000000u) ? g_invfeat : feat;
        const float* t2 = (p2 & 0x80000000u) ? g_invfeat : feat;
        const float* t3 = (p3 & 0x80000000u) ? g_invfeat : feat;
        float4 v0 = *reinterpret_cast<const float4*>(t0 + (size_t)(p0 & 0x7FFFFFFFu) * H + lane * 4);
        float4 v1 = *reinterpret_cast<const float4*>(t1 + (size_t)(p1 & 0x7FFFFFFFu) * H + lane * 4);
        float4 v2 = *reinterpret_cast<const float4*>(t2 + (size_t)(p2 & 0x7FFFFFFFu) * H + lane * 4);
        float4 v3 = *reinterpret_cast<const float4*>(t3 + (size_t)(p3 & 0x7FFFFFFFu) * H + lane * 4);
        s.x += v0.x + v1.x + v2.x + v3.x;
        s.y += v0.y + v1.y + v2.y + v3.y;
        s.z += v0.z + v1.z + v2.z + v3.z;
        s.w += v0.w + v1.w + v2.w + v3.w;
    }
    for (; i < end; i++) {
        unsigned int p = g_perm[i];
        const float* tab = (p & 0x80000000u) ? g_invfeat : feat;
        float4 v = *reinterpret_cast<const float4*>(tab + (size_t)(p & 0x7FFFFFFFu) * H + lane * 4);
        s.x += v.x; s.y += v.y; s.z += v.z; s.w += v.w;
    }
    int deg = end - beg;
    float sc = 1.f / (float)max(deg, 1);
    s.x *= sc; s.y *= sc; s.z *= sc; s.w *= sc;
    *reinterpret_cast<float4*>(g_nsum + (size_t)w * H + lane * 4) = s;
}

// ---------------------------------------------------------------------------
// warp per row: inv==1 rows -> append to index list; inv==0 rows -> copy res->out
__global__ __launch_bounds__(256) void compact_kernel(
    const int* __restrict__ inv, const float* __restrict__ res,
    float* __restrict__ out, int n) {
    int w    = (blockIdx.x * blockDim.x + threadIdx.x) >> 5;
    int lane = threadIdx.x & 31;
    int nw   = (gridDim.x * blockDim.x) >> 5;
    for (int row = w; row < n; row += nw) {
        if (inv[row] == 1) {
            if (lane == 0) {
                int p = atomicAdd(&g_cnt, 1);
                g_idx[p] = row;
            }
        } else {
            float4 v = reinterpret_cast<const float4*>(res + (size_t)row * H)[lane];
            reinterpret_cast<float4*>(out + (size_t)row * H)[lane] = v;
        }
    }
}

// ---------------------------------------------------------------------------
// Fused 3-layer MLP: bf16 split mma.sync, activations register-resident.
__global__ __launch_bounds__(256, 2) void mlp3_mma(
    const float* __restrict__ in, float* __restrict__ out,
    const float* __restrict__ w1, const float* __restrict__ b1,
    const float* __restrict__ w2, const float* __restrict__ b2,
    const float* __restrict__ w3, const float* __restrict__ b3,
    const int* __restrict__ rowidx, const int* __restrict__ cnt_dev,
    int nrows) {
    extern __shared__ char wp[];
    const uint32_t sb = smem_u32(wp);

    const int tid  = threadIdx.x;
    const int wid  = tid >> 5;
    const int lane = tid & 31;

    // ---- stage weights bf16 hi/lo, [n][k] row-major padded ----
    for (int idx = tid; idx < HH * H; idx += 256) {      // w1 [64][128]
        int n = idx >> 7, k = idx & 127;
        float v = w1[idx];
        __nv_bfloat16 h = __float2bfloat16_rn(v);
        __nv_bfloat16 l = __float2bfloat16_rn(v - __bfloat162float(h));
        *(__nv_bfloat16*)(wp + OW1H + n * XSB + k * 2) = h;
        *(__nv_bfloat16*)(wp + OW1L + n * XSB + k * 2) = l;
    }
    for (int idx = tid; idx < HH * HH; idx += 256) {     // w2 [64][64]
        int n = idx >> 6, k = idx & 63;
        float v = w2[idx];
        __nv_bfloat16 h = __float2bfloat16_rn(v);
        __nv_bfloat16 l = __float2bfloat16_rn(v - __bfloat162float(h));
        *(__nv_bfloat16*)(wp + OW2H + n * HSB + k * 2) = h;
        *(__nv_bfloat16*)(wp + OW2L + n * HSB + k * 2) = l;
    }
    for (int idx = tid; idx < H * HH; idx += 256) {      // w3 [128][64]
        int n = idx >> 6, k = idx & 63;
        float v = w3[idx];
        __nv_bfloat16 h = __float2bfloat16_rn(v);
        __nv_bfloat16 l = __float2bfloat16_rn(v - __bfloat162float(h));
        *(__nv_bfloat16*)(wp + OW3H + n * HSB + k * 2) = h;
        *(__nv_bfloat16*)(wp + OW3L + n * HSB + k * 2) = l;
    }
    if (tid < HH) {
        ((float*)(wp + OB1))[tid] = b1[tid];
        ((float*)(wp + OB2))[tid] = b2[tid];
    }
    if (tid < H) ((float*)(wp + OB3))[tid] = b3[tid];
    __syncthreads();

    const float* b1s = (const float*)(wp + OB1);
    const float* b2s = (const float*)(wp + OB2);
    const float* b3s = (const float*)(wp + OB3);

    const int m0 = wid * 16;
    const int g  = lane >> 2;        // 0..7
    const int t  = lane & 3;         // 0..3

    // B-frag ldmatrix lane addressing
    const int b_row = (lane & 7) + ((lane >> 4) << 3);
    const int b_kof = ((lane >> 3) & 1) * 16;
    const uint32_t bw1h = sb + OW1H + b_row * XSB + b_kof;
    const uint32_t bw1l = sb + OW1L + b_row * XSB + b_kof;
    const uint32_t bw2h = sb + OW2H + b_row * HSB + b_kof;
    const uint32_t bw2l = sb + OW2L + b_row * HSB + b_kof;
    const uint32_t bw3h = sb + OW3H + b_row * HSB + b_kof;
    const uint32_t bw3l = sb + OW3L + b_row * HSB + b_kof;

    const int nr = (cnt_dev != nullptr) ? *cnt_dev : nrows;
    const int ntiles = (nr + TM - 1) / TM;

    for (int tile = blockIdx.x; tile < ntiles; tile += gridDim.x) {
        const int row0  = tile * TM;
        const int rowg_l  = row0 + m0 + g;
        const int rowg8_l = rowg_l + 8;
        const bool okg  = rowg_l  < nr;
        const bool okg8 = rowg8_l < nr;
        const int rowg  = (rowidx != nullptr) ? (okg  ? rowidx[rowg_l]  : 0) : rowg_l;
        const int rowg8 = (rowidx != nullptr) ? (okg8 ? rowidx[rowg8_l] : 0) : rowg8_l;

        const float* rp  = in + (size_t)rowg  * H + 2 * t;
        const float* rp8 = in + (size_t)rowg8 * H + 2 * t;

        // ================= layer 1: K=128, N=64 =================
        float acc[8][4] = {};
        #pragma unroll
        for (int kt = 0; kt < 8; kt++) {
            float2 p0 = okg  ? *(const float2*)(rp  + kt * 16)     : make_float2(0.f, 0.f);
            float2 p1 = okg8 ? *(const float2*)(rp8 + kt * 16)     : make_float2(0.f, 0.f);
            float2 p2 = okg  ? *(const float2*)(rp  + kt * 16 + 8) : make_float2(0.f, 0.f);
            float2 p3 = okg8 ? *(const float2*)(rp8 + kt * 16 + 8) : make_float2(0.f, 0.f);
            uint32_t ah[4], al[4];
            split2(p0.x, p0.y, ah[0], al[0]);
            split2(p1.x, p1.y, ah[1], al[1]);
            split2(p2.x, p2.y, ah[2], al[2]);
            split2(p3.x, p3.y, ah[3], al[3]);

            uint32_t bh[4][4], bl[4][4];
            #pragma unroll
            for (int np = 0; np < 4; np++) {
                ldm_x4(bw1h + np * 16 * XSB + kt * 32, bh[np]);
                ldm_x4(bw1l + np * 16 * XSB + kt * 32, bl[np]);
            }
            sweep(acc, ah, bh);
            sweep(acc, al, bh);
            sweep(acc, ah, bl);
        }

        // epi 1 -> layer-2 A frags (registers)
        uint32_t a2h[4][4], a2l[4][4];
        epi_frag(acc, b1s, t, a2h, a2l);

        // ================= layer 2: K=64, N=64 =================
        float acc2[8][4] = {};
        #pragma unroll
        for (int kt = 0; kt < 4; kt++) {
            uint32_t bh[4][4], bl[4][4];
            #pragma unroll
            for (int np = 0; np < 4; np++) {
                ldm_x4(bw2h + np * 16 * HSB + kt * 32, bh[np]);
                ldm_x4(bw2l + np * 16 * HSB + kt * 32, bl[np]);
            }
            sweep(acc2, a2h[kt], bh);
            sweep(acc2, a2l[kt], bh);
            sweep(acc2, a2h[kt], bl);
        }

        // epi 2 -> layer-3 A frags
        uint32_t a3h[4][4], a3l[4][4];
        epi_frag(acc2, b2s, t, a3h, a3l);

        // ================= layer 3: K=64, N=128 (two halves) =================
        #pragma unroll
        for (int nh = 0; nh < 2; nh++) {
            float acc3[8][4] = {};
            #pragma unroll
            for (int kt = 0; kt < 4; kt++) {
                uint32_t bh[4][4], bl[4][4];
                #pragma unroll
                for (int np = 0; np < 4; np++) {
                    uint32_t boff = (nh * 64 + np * 16) * HSB + kt * 32;
                    ldm_x4(bw3h + boff, bh[np]);
                    ldm_x4(bw3l + boff, bl[np]);
                }
                sweep(acc3, a3h[kt], bh);
                sweep(acc3, a3l[kt], bh);
                sweep(acc3, a3h[kt], bl);
            }
            #pragma unroll
            for (int nt = 0; nt < 8; nt++) {
                int col = nh * 64 + nt * 8 + 2 * t;
                float bx = b3s[col], by = b3s[col + 1];
                if (okg) {
                    float2 v = make_float2(acc3[nt][0] + bx, acc3[nt][1] + by);
                    *reinterpret_cast<float2*>(out + (size_t)rowg * H + col) = v;
                }
                if (okg8) {
                    float2 v = make_float2(acc3[nt][2] + bx, acc3[nt][3] + by);
                    *reinterpret_cast<float2*>(out + (size_t)rowg8 * H + col) = v;
                }
            }
        }
    }
}

// ---------------------------------------------------------------------------
extern "C" void kernel_launch(void* const* d_in, const int* in_sizes, int n_in,
                              void* d_out, int out_size) {
    const float* feat   = (const float*)d_in[0];
    const int*   src    = (const int*)d_in[1];
    const int*   dst    = (const int*)d_in[2];
    const int*   r      = (const int*)d_in[3];
    const int*   inv    = (const int*)d_in[4];
    const float* inv_w1 = (const float*)d_in[5];
    const float* inv_b1 = (const float*)d_in[6];
    const float* inv_w2 = (const float*)d_in[7];
    const float* inv_b2 = (const float*)d_in[8];
    const float* inv_w3 = (const float*)d_in[9];
    const float* inv_b3 = (const float*)d_in[10];
    const float* and_w1 = (const float*)d_in[11];
    const float* and_b1 = (const float*)d_in[12];
    const float* and_w2 = (const float*)d_in[13];
    const float* and_b2 = (const float*)d_in[14];
    const float* and_w3 = (const float*)d_in[15];
    const float* and_b3 = (const float*)d_in[16];

    const int n = in_sizes[0] / H;
    const int e = in_sizes[1];

    float *invfeat, *nsum, *res;
    int *idxl, *cnt;
    cudaGetSymbolAddress((void**)&invfeat, g_invfeat);
    cudaGetSymbolAddress((void**)&nsum,    g_nsum);
    cudaGetSymbolAddress((void**)&res,     g_res);
    cudaGetSymbolAddress((void**)&idxl,    g_idx);
    cudaGetSymbolAddress((void**)&cnt,     g_cnt);

    cudaFuncSetAttribute(mlp3_mma, cudaFuncAttributeMaxDynamicSharedMemorySize, SMEM_BYTES);

    const int egrid = (e + 255) / 256;
    const int ngrid = (n + 255) / 256;
    const int sblk  = (n + SCB - 1) / SCB;

    // 1. CSR build: zero -> histogram -> 3-phase scan -> fill
    zero_kernel<<<ngrid, 256>>>(n);
    hist_kernel<<<egrid, 256>>>(dst, e);
    scan_reduce_kernel<<<sblk, 1024>>>(n);
    scan_base_kernel<<<1, 32>>>();
    scan_write_kernel<<<sblk, 1024>>>(n);
    fill_kernel<<<egrid, 256>>>(src, dst, r, e);

    const int ntiles = (n + TM - 1) / TM;
    const int mgrid  = ntiles < 296 ? ntiles : 296;   // 2 CTAs/SM

    // 2. inv_feat = mlp3_inv(feat)
    mlp3_mma<<<mgrid, 256, SMEM_BYTES>>>(
        feat, invfeat, inv_w1, inv_b1, inv_w2, inv_b2, inv_w3, inv_b3,
        nullptr, nullptr, n);

    // 3. CSR aggregation: nsum = mean of messages per dst (no atomics)
    aggregate_kernel<<<(n * 32 + 255) / 256, 256>>>(feat, n);

    // 4. res = mlp3_and(nsum)
    mlp3_mma<<<mgrid, 256, SMEM_BYTES>>>(
        nsum, res, and_w1, and_b1, and_w2, and_b2, and_w3, and_b3,
        nullptr, nullptr, n);

    // 5a. compact inv==1 rows; copy inv==0 rows res->out
    compact_kernel<<<1024, 256>>>(inv, res, (float*)d_out, n);

    // 5b. out[idx] = mlp3_inv(res[idx]) for compacted rows
    mlp3_mma<<<296, 256, SMEM_BYTES>>>(
        res, (float*)d_out, inv_w1, inv_b1, inv_w2, inv_b2, inv_w3, inv_b3,
        idxl, cnt, n);
}